// round 7
// baseline (speedup 1.0000x reference)
#include <cuda_runtime.h>
#include <cuda_bf16.h>

// Problem constants (fixed by the reference)
#define BATCH 16
#define MCTRL 64
#define NCTRL 64
#define DEG   3
#define LKNOT 68                // M + P + 1
#define NSPAN (LKNOT - 2*DEG)   // 62 candidate spans
#define OUTU  256
#define OUTV  256
#define U_PER 4                 // u samples per block (task = thread: 4*64 = 256)

// Fully fused, latency-minimized kernel.
// Grid: (OUTU/U_PER, BATCH) = (64, 16) = 1024 blocks x 256 threads.
//
//   1. Warp 0 alone: load 68 knots, pure-shfl inclusive scan (lane l holds
//      elements l, l+32, l+64), normalize -> K[] in smem. One barrier.
//      (Nu == Nv and uspan == vspan: the reference builds V from knot_u and
//       u/v linspaces + degrees are identical -> one table serves both axes.)
//   2. Every thread computes its FOLD task's u-span (6-step binary search) and
//      immediately issues its 4 LDG.128 control-point loads, THEN computes its
//      own sample-t basis (span + Cox-de Boor) while the loads are in flight.
//   3. Publish the block's 4 u-bases to smem, barrier, fold into stmp rows.
//   4. Stage B: per-thread v contraction (v == t, basis in registers):
//      4 LDS.128 + 12 FMA + 3 STG per point.
//
// Span search correctness: the reference predicate (tv - K[s+DEG]) > 1e-8 is
// prefix-true in s (K monotone non-decreasing; fp subtract with fixed minuend
// is monotone), so argmin-with-first-tie == prefix-count - 1; the binary
// search probes the identical fp expression.
__global__ void __launch_bounds__(256) surf_kernel(const float* __restrict__ ctrl,
                                                   const float* __restrict__ knot_u,
                                                   float* __restrict__ out) {
    const int u0 = blockIdx.x * U_PER;
    const int b  = blockIdx.y;
    const int t  = threadIdx.x;

    __shared__ float  K[LKNOT];           // normalized knots
    __shared__ float4 sbu[U_PER];         // basis for this block's u samples
    __shared__ float4 stmp[U_PER][NCTRL]; // u-folded rows (4 KB)

    // ---- 1. knots + one-warp shfl scan + normalize ------------------------
    if (t < 32) {
        const float* kn = knot_u + b * LKNOT;
        const int l = t;
        float a0 = kn[l];
        float a1 = kn[l + 32];
        float a2 = (l < 4) ? kn[l + 64] : 0.f;

        #pragma unroll
        for (int off = 1; off < 32; off <<= 1) {
            const float n0 = __shfl_up_sync(0xffffffffu, a0, off);
            const float n1 = __shfl_up_sync(0xffffffffu, a1, off);
            const float n2 = __shfl_up_sync(0xffffffffu, a2, off);
            if (l >= off) { a0 += n0; a1 += n1; a2 += n2; }
        }
        const float tot0 = __shfl_sync(0xffffffffu, a0, 31);
        const float tot1 = __shfl_sync(0xffffffffu, a1, 31);
        const float cs2_3 = __shfl_sync(0xffffffffu, a2, 3);  // sum of last 4

        const float c0    = __shfl_sync(0xffffffffu, a0, 0);  // cs[0] = kn[0]
        const float clast = tot0 + tot1 + cs2_3;              // cs[67]
        const float inv   = 1.f / (clast - c0);

        K[l]      = (a0 - c0) * inv * ((clast - c0) * inv);   // see note below
        // NOTE: the reference divides; replicate exactly with division:
        K[l]      = (a0 - c0) / (clast - c0);
        K[l + 32] = (tot0 + a1 - c0) / (clast - c0);
        if (l < 4) K[l + 64] = (tot0 + tot1 + a2 - c0) / (clast - c0);
    }
    __syncthreads();

    // linspace(1e-5, 1-1e-5, 256): start + i*step, endpoint exact.
    const float start = 1e-5f;
    const float stop  = 1.0f - 1e-5f;
    const float step  = (stop - start) / (float)(OUTU - 1);

    // ---- 2a. fold-task span + control-point prefetch ----------------------
    const int up = t >> 6;        // 0..3
    const int n  = t & 63;        // 0..63
    const int uu = u0 + up;
    float tu = start + (float)uu * step;
    if (uu == OUTU - 1) tu = stop;

    int cu = 0;
    #pragma unroll
    for (int s = 32; s; s >>= 1) {
        const int ns = cu + s;
        if (ns <= NSPAN && ((tu - K[ns - 1 + DEG]) > 1e-8f)) cu = ns;
    }
    const int su = cu - 1;        // spanU - DEG

    const float4* cp = reinterpret_cast<const float4*>(ctrl)
                     + (size_t)b * MCTRL * NCTRL + n;
    const float4 p0 = cp[(su + 0) * NCTRL];   // loads issue here,
    const float4 p1 = cp[(su + 1) * NCTRL];   // consumed after own-basis
    const float4 p2 = cp[(su + 2) * NCTRL];   // compute below (latency hidden)
    const float4 p3 = cp[(su + 3) * NCTRL];

    // ---- 2b. own-sample basis (registers), overlapped with the LDGs -------
    float tv = start + (float)t * step;
    if (t == OUTU - 1) tv = stop;

    int cnt = 0;
    #pragma unroll
    for (int s = 32; s; s >>= 1) {
        const int ns = cnt + s;
        if (ns <= NSPAN && ((tv - K[ns - 1 + DEG]) > 1e-8f)) cnt = ns;
    }
    const int span = DEG + cnt - 1;

    // Cox-de Boor (mirrors the reference arithmetic, including the
    // (K1 - t) + (t - K2) denominator form).
    float Nb[DEG + 1];
    Nb[0] = 1.f;
    #pragma unroll
    for (int k = 1; k <= DEG; k++) {
        float saved = 0.f;
        #pragma unroll
        for (int r = 0; r < k; r++) {
            const float K1 = K[span + r + 1];
            const float K2 = K[span + 1 - k + r];
            const float denom = (K1 - tv) + (tv - K2);
            const float temp  = Nb[r] / denom;
            Nb[r] = saved + (K1 - tv) * temp;
            saved = (tv - K2) * temp;
        }
        Nb[k] = saved;
    }

    // ---- 3. publish block u-bases, fold ------------------------------------
    {
        const unsigned du = (unsigned)(t - u0);
        if (du < U_PER)
            sbu[du] = make_float4(Nb[0], Nb[1], Nb[2], Nb[3]);
    }
    __syncthreads();

    {
        const float4 nu = sbu[up];
        float4 r;
        r.x = fmaf(nu.x, p0.x, fmaf(nu.y, p1.x, fmaf(nu.z, p2.x, nu.w * p3.x)));
        r.y = fmaf(nu.x, p0.y, fmaf(nu.y, p1.y, fmaf(nu.z, p2.y, nu.w * p3.y)));
        r.z = fmaf(nu.x, p0.z, fmaf(nu.y, p1.z, fmaf(nu.z, p2.z, nu.w * p3.z)));
        r.w = 0.f;
        stmp[up][n] = r;
    }
    __syncthreads();

    // ---- 4. Stage B: per-v contraction (v == t) ----------------------------
    const int   sv  = span - DEG;
    const float nv0 = Nb[0], nv1 = Nb[1], nv2 = Nb[2], nv3 = Nb[3];

    float* op = out + (((size_t)b * OUTU + u0) * OUTV + t) * 3;

    #pragma unroll
    for (int w = 0; w < U_PER; w++) {
        const float4 c0 = stmp[w][sv + 0];
        const float4 c1 = stmp[w][sv + 1];
        const float4 c2 = stmp[w][sv + 2];
        const float4 c3 = stmp[w][sv + 3];

        const float ax = fmaf(nv0, c0.x, fmaf(nv1, c1.x, fmaf(nv2, c2.x, nv3 * c3.x)));
        const float ay = fmaf(nv0, c0.y, fmaf(nv1, c1.y, fmaf(nv2, c2.y, nv3 * c3.y)));
        const float az = fmaf(nv0, c0.z, fmaf(nv1, c1.z, fmaf(nv2, c2.z, nv3 * c3.z)));

        float* o = op + (size_t)w * OUTV * 3;
        o[0] = ax;
        o[1] = ay;
        o[2] = az;
    }
}

// ---------------------------------------------------------------------------
// Launch. Inputs per metadata order: ctrl_pts [16,64,64,4] f32,
// knot_u [16,68] f32, knot_v [16,68] f32 (unused — the reference builds both
// directions from knot_u).
// ---------------------------------------------------------------------------
extern "C" void kernel_launch(void* const* d_in, const int* in_sizes, int n_in,
                              void* d_out, int out_size) {
    const float* ctrl   = (const float*)d_in[0];
    const float* knot_u = (const float*)d_in[1];
    float* out = (float*)d_out;

    surf_kernel<<<dim3(OUTU / U_PER, BATCH), 256>>>(ctrl, knot_u, out);
}